// round 3
// baseline (speedup 1.0000x reference)
#include <cuda_runtime.h>
#include <cstdint>

#define N_NODES 2048
#define N_EDGES 8192
#define EDGE_DIM 10
#define EH 32
#define HID 160
#define NW (HID*HID)                 // 25600
#define COL_B2 (EH*HID)              // 5120
#define COL_ROOT (EH*HID + HID)      // 5280
#define NCOLS (EH*HID + HID + HID)   // 5440

// ---------------- device scratch ----------------
__device__ float g_A[2][HID * NCOLS];
__device__ float g_h[2][N_EDGES * EH];
__device__ float g_Y[N_NODES * NCOLS];
__device__ float g_accum[N_NODES * HID];
__device__ float g_x[2][N_NODES * HID];
__device__ int   g_cnt[N_NODES];          // in-degree (dst counts)
__device__ int   g_dst[N_EDGES];
__device__ int   g_csr_off[N_NODES + 1];  // CSR by src
__device__ int   g_csr_edge[N_EDGES];

// =====================================================================
// Preprocessing: ONE block does int64-detect, edge decode, src/dst
// counts, scan, CSR fill.
// =====================================================================
__global__ __launch_bounds__(1024) void prep_kernel(const void* __restrict__ eiraw) {
    __shared__ int s_flag;
    __shared__ int s_cs[N_NODES];     // src counts
    __shared__ int s_cd[N_NODES];     // dst counts
    __shared__ int s_a[N_NODES];      // scan ping
    __shared__ int s_b[N_NODES];      // scan pong / heads
    int t = threadIdx.x;

    for (int i = t; i < N_NODES; i += 1024) { s_cs[i] = 0; s_cd[i] = 0; }
    if (t == 0) s_flag = 0;
    __syncthreads();

    // detect storage width: int64 => odd 32-bit words all zero
    const int* raw = (const int*)eiraw;
    int f = 0;
    for (int i = t; i < N_EDGES; i += 1024)
        if (raw[2 * i + 1] != 0) f = 1;
    if (f) atomicOr(&s_flag, 1);
    __syncthreads();
    int flag = s_flag;

    // decode 8 edges per thread
    int es[8], ed[8];
    #pragma unroll
    for (int j = 0; j < 8; j++) {
        int e = t + 1024 * j;
        if (flag) {
            es[j] = raw[e]; ed[j] = raw[N_EDGES + e];
        } else {
            const long long* p = (const long long*)eiraw;
            es[j] = (int)p[e]; ed[j] = (int)p[N_EDGES + e];
        }
        atomicAdd(&s_cs[es[j]], 1);
        atomicAdd(&s_cd[ed[j]], 1);
        g_dst[e] = ed[j];
    }
    __syncthreads();

    for (int i = t; i < N_NODES; i += 1024) { g_cnt[i] = s_cd[i]; s_a[i] = s_cs[i]; }
    __syncthreads();

    // inclusive Hillis-Steele scan of s_a (2048 elems)
    int* pa = s_a; int* pb = s_b;
    for (int d = 1; d < N_NODES; d <<= 1) {
        for (int i = t; i < N_NODES; i += 1024)
            pb[i] = pa[i] + (i >= d ? pa[i - d] : 0);
        __syncthreads();
        int* tmp = pa; pa = pb; pb = tmp;
    }
    // exclusive offsets -> gmem + heads (reuse pb)
    for (int i = t; i < N_NODES; i += 1024) {
        int off = (i == 0) ? 0 : pa[i - 1];
        g_csr_off[i] = off;
        pb[i] = off;
    }
    if (t == 0) g_csr_off[N_NODES] = N_EDGES;
    __syncthreads();

    // fill CSR
    #pragma unroll
    for (int j = 0; j < 8; j++) {
        int e = t + 1024 * j;
        int pos = atomicAdd(&pb[es[j]], 1);
        g_csr_edge[pos] = e;
    }
}

// =====================================================================
// Params mega-kernel: build_A (both slots) + edge MLP h (both slots)
// + zero accum, split by blockIdx.
// =====================================================================
#define NA_BLOCKS ((HID * NCOLS + 255) / 256)        // 3400
#define H_BLOCKS  (N_EDGES / 8)                      // 1024
#define Z_BLOCKS  ((N_NODES * HID + 255) / 256)      // 1280

__global__ __launch_bounds__(256) void params_kernel(
        const float* __restrict__ w2a, const float* __restrict__ b2a,
        const float* __restrict__ roota,
        const float* __restrict__ w2b, const float* __restrict__ b2b,
        const float* __restrict__ rootb,
        const float* __restrict__ ea,
        const float* __restrict__ w1a, const float* __restrict__ b1a,
        const float* __restrict__ w1b, const float* __restrict__ b1b) {
    __shared__ float sw[EDGE_DIM * EH];
    __shared__ float sb[EH];
    int b = blockIdx.x;
    int t = threadIdx.x;

    if (b < 2 * NA_BLOCKS) {
        int slot = (b >= NA_BLOCKS);
        const float* w2   = slot ? w2b : w2a;
        const float* b2   = slot ? b2b : b2a;
        const float* root = slot ? rootb : roota;
        int idx = (b - slot * NA_BLOCKS) * 256 + t;
        if (idx < HID * NCOLS) {
            int i = idx / NCOLS;
            int c = idx % NCOLS;
            float v;
            if (c < COL_B2) {
                int k = c / HID, o = c % HID;
                v = w2[k * NW + i * HID + o];
            } else if (c < COL_ROOT) {
                v = b2[i * HID + (c - COL_B2)];
            } else {
                v = root[i * HID + (c - COL_ROOT)];
            }
            g_A[slot][idx] = v;
        }
    } else if (b < 2 * NA_BLOCKS + 2 * H_BLOCKS) {
        int bb = b - 2 * NA_BLOCKS;
        int slot = (bb >= H_BLOCKS);
        const float* w1 = slot ? w1b : w1a;
        const float* b1 = slot ? b1b : b1a;
        for (int i = t; i < EDGE_DIM * EH; i += 256) sw[i] = w1[i];
        if (t < EH) sb[t] = b1[t];
        __syncthreads();
        int j  = t & 31;
        int e  = (bb - slot * H_BLOCKS) * 8 + (t >> 5);
        float acc = sb[j];
        #pragma unroll
        for (int d = 0; d < EDGE_DIM; d++)
            acc += ea[e * EDGE_DIM + d] * sw[d * EH + j];
        g_h[slot][e * EH + j] = fmaxf(acc, 0.0f);
    } else {
        int idx = (b - 2 * NA_BLOCKS - 2 * H_BLOCKS) * 256 + t;
        if (idx < N_NODES * HID) g_accum[idx] = 0.0f;
    }
}

// =====================================================================
// TF32 GEMM, cp.async double-buffered. Y[2048,5440] = X[2048,160]@A
// =====================================================================
#define BM 128
#define BN 128
#define BK 32
#define AS_STRIDE 36
#define BS_STRIDE 136
#define AS_ELEMS (BM * AS_STRIDE)     // 4608
#define BS_ELEMS (BK * BS_STRIDE)     // 4352
#define GEMM_SMEM ((AS_ELEMS + BS_ELEMS) * 2 * 4)   // 71680 B

__device__ __forceinline__ uint32_t f2tf32(float f) {
    uint32_t u;
    asm("cvt.rna.tf32.f32 %0, %1;" : "=r"(u) : "f"(f));
    return u;
}

__device__ __forceinline__ void mma_tf32(float* d, const uint32_t* a, const uint32_t* b) {
    asm volatile(
        "mma.sync.aligned.m16n8k8.row.col.f32.tf32.tf32.f32 "
        "{%0,%1,%2,%3}, {%4,%5,%6,%7}, {%8,%9}, {%0,%1,%2,%3};"
        : "+f"(d[0]), "+f"(d[1]), "+f"(d[2]), "+f"(d[3])
        : "r"(a[0]), "r"(a[1]), "r"(a[2]), "r"(a[3]), "r"(b[0]), "r"(b[1]));
}

__global__ __launch_bounds__(256, 2) void gemm_kernel(const float* __restrict__ xin,
                                                      int xsel, int aslot) {
    const float* __restrict__ X  = (xsel < 0) ? xin : g_x[xsel];
    const float* __restrict__ Bm = g_A[aslot];

    extern __shared__ float smem[];
    float* As = smem;                       // [2][AS_ELEMS]
    float* Bs = smem + 2 * AS_ELEMS;        // [2][BS_ELEMS]

    int tid  = threadIdx.x;
    int lane = tid & 31;
    int w    = tid >> 5;
    int wm   = w & 1;
    int wn   = w >> 1;
    int g    = lane >> 2;
    int tig  = lane & 3;

    int n0 = blockIdx.x * BN;
    int m0 = blockIdx.y * BM;

    float acc[4][4][4];
    #pragma unroll
    for (int i = 0; i < 4; i++)
        #pragma unroll
        for (int j = 0; j < 4; j++)
            #pragma unroll
            for (int r = 0; r < 4; r++) acc[i][j][r] = 0.0f;

    // stage tile (k0) into buffer buf via cp.async
    auto stage = [&](int buf, int k0) {
        float* ad = As + buf * AS_ELEMS;
        float* bd = Bs + buf * BS_ELEMS;
        #pragma unroll
        for (int i = 0; i < 4; i++) {
            int s   = tid + 256 * i;
            int row = s >> 3;
            int col = (s & 7) * 4;
            uint32_t dst = (uint32_t)__cvta_generic_to_shared(&ad[row * AS_STRIDE + col]);
            const float* src = X + (size_t)(m0 + row) * HID + k0 + col;
            asm volatile("cp.async.cg.shared.global [%0], [%1], 16;"
                         :: "r"(dst), "l"(src));
        }
        #pragma unroll
        for (int i = 0; i < 4; i++) {
            int s   = tid + 256 * i;
            int row = s >> 5;
            int col = (s & 31) * 4;
            int gc  = n0 + col;
            uint32_t dst = (uint32_t)__cvta_generic_to_shared(&bd[row * BS_STRIDE + col]);
            const float* src = Bm + (size_t)(k0 + row) * NCOLS + gc;
            int bytes = (gc < NCOLS) ? 16 : 0;
            asm volatile("cp.async.cg.shared.global [%0], [%1], 16, %2;"
                         :: "r"(dst), "l"(src), "r"(bytes));
        }
        asm volatile("cp.async.commit_group;");
    };

    stage(0, 0);

    for (int it = 0; it < 5; it++) {
        if (it < 4) {
            stage((it + 1) & 1, (it + 1) * BK);
            asm volatile("cp.async.wait_group 1;");
        } else {
            asm volatile("cp.async.wait_group 0;");
        }
        __syncthreads();

        const float* as = As + (it & 1) * AS_ELEMS;
        const float* bs = Bs + (it & 1) * BS_ELEMS;

        #pragma unroll
        for (int ks = 0; ks < 4; ks++) {
            int ck = ks * 8;
            uint32_t af[4][4];
            #pragma unroll
            for (int mt = 0; mt < 4; mt++) {
                int rb = wm * 64 + mt * 16;
                af[mt][0] = f2tf32(as[(rb + g)     * AS_STRIDE + ck + tig]);
                af[mt][1] = f2tf32(as[(rb + g + 8) * AS_STRIDE + ck + tig]);
                af[mt][2] = f2tf32(as[(rb + g)     * AS_STRIDE + ck + tig + 4]);
                af[mt][3] = f2tf32(as[(rb + g + 8) * AS_STRIDE + ck + tig + 4]);
            }
            uint32_t bf[4][2];
            #pragma unroll
            for (int nt = 0; nt < 4; nt++) {
                int nc = wn * 32 + nt * 8 + g;
                bf[nt][0] = f2tf32(bs[(ck + tig)     * BS_STRIDE + nc]);
                bf[nt][1] = f2tf32(bs[(ck + tig + 4) * BS_STRIDE + nc]);
            }
            #pragma unroll
            for (int mt = 0; mt < 4; mt++)
                #pragma unroll
                for (int nt = 0; nt < 4; nt++)
                    mma_tf32(acc[mt][nt], af[mt], bf[nt]);
        }
        __syncthreads();
    }

    #pragma unroll
    for (int mt = 0; mt < 4; mt++) {
        int row = m0 + wm * 64 + mt * 16 + g;
        #pragma unroll
        for (int nt = 0; nt < 4; nt++) {
            int col = n0 + wn * 32 + nt * 8 + 2 * tig;
            if (col < NCOLS) {
                *(float2*)(g_Y + (size_t)row * NCOLS + col) =
                    make_float2(acc[mt][nt][0], acc[mt][nt][1]);
                *(float2*)(g_Y + (size_t)(row + 8) * NCOLS + col) =
                    make_float2(acc[mt][nt][2], acc[mt][nt][3]);
            }
        }
    }
}

// =====================================================================
// Edge message + scatter, CSR-by-src: one block per node, Y row cached
// in smem once, served to all out-edges.
// =====================================================================
__global__ __launch_bounds__(HID) void edge_kernel(int slot) {
    __shared__ float sY[COL_ROOT];   // 5280 floats = 21120 B
    __shared__ float sh[EH];
    int n = blockIdx.x;
    int t = threadIdx.x;
    int beg = g_csr_off[n];
    int end = g_csr_off[n + 1];
    if (beg == end) return;

    const float* Yr = g_Y + (size_t)n * NCOLS;
    for (int i = t; i < COL_ROOT; i += HID) sY[i] = Yr[i];

    for (int j = beg; j < end; j++) {
        int e = g_csr_edge[j];
        if (t < EH) sh[t] = g_h[slot][e * EH + t];
        __syncthreads();
        float msg = sY[COL_B2 + t];
        #pragma unroll
        for (int k = 0; k < EH; k++) msg += sh[k] * sY[k * HID + t];
        atomicAdd(&g_accum[g_dst[e] * HID + t], msg);
        __syncthreads();
    }
}

// =====================================================================
// Finalize: out = act(accum/max(cnt,1) + root_term + bias); re-zero accum.
// =====================================================================
__global__ void final_kernel(const float* __restrict__ bias, int outsel,
                             float* __restrict__ dout, int relu) {
    int idx = blockIdx.x * blockDim.x + threadIdx.x;
    if (idx >= N_NODES * HID) return;
    int n = idx / HID, o = idx % HID;
    float inv = 1.0f / fmaxf((float)g_cnt[n], 1.0f);
    float v = g_accum[idx] * inv + g_Y[(size_t)n * NCOLS + COL_ROOT + o] + bias[o];
    if (relu) v = fmaxf(v, 0.0f);
    g_accum[idx] = 0.0f;     // ready for next layer
    float* dst = (outsel == 2) ? dout : g_x[outsel];
    dst[idx] = v;
}

// =====================================================================
// launch
// =====================================================================
extern "C" void kernel_launch(void* const* d_in, const int* in_sizes, int n_in,
                              void* d_out, int out_size) {
    const float* x       = (const float*)d_in[0];
    const float* ea      = (const float*)d_in[1];
    const float* w1_a    = (const float*)d_in[2];
    const float* b1_a    = (const float*)d_in[3];
    const float* w2_a    = (const float*)d_in[4];
    const float* b2_a    = (const float*)d_in[5];
    const float* root_a  = (const float*)d_in[6];
    const float* bias_a  = (const float*)d_in[7];
    const float* w1_b    = (const float*)d_in[8];
    const float* b1_b    = (const float*)d_in[9];
    const float* w2_b    = (const float*)d_in[10];
    const float* b2_b    = (const float*)d_in[11];
    const float* root_b  = (const float*)d_in[12];
    const float* bias_b  = (const float*)d_in[13];
    const void*  eidx    = d_in[14];
    float* out = (float*)d_out;

    static int smem_set = 0;
    if (!smem_set) {
        cudaFuncSetAttribute(gemm_kernel,
                             cudaFuncAttributeMaxDynamicSharedMemorySize, GEMM_SMEM);
        smem_set = 1;
    }

    prep_kernel<<<1, 1024>>>(eidx);
    params_kernel<<<2 * NA_BLOCKS + 2 * H_BLOCKS + Z_BLOCKS, 256>>>(
        w2_a, b2_a, root_a, w2_b, b2_b, root_b, ea, w1_a, b1_a, w1_b, b1_b);

    dim3 gemm_grid((NCOLS + BN - 1) / BN, N_NODES / BM);   // (43, 16)
    int nh = N_NODES * HID;
    int fb = (nh + 255) / 256;

    // layer 0 (params a), relu
    gemm_kernel<<<gemm_grid, 256, GEMM_SMEM>>>(x, -1, 0);
    edge_kernel<<<N_NODES, HID>>>(0);
    final_kernel<<<fb, 256>>>(bias_a, 0, out, 1);

    // layer 1 (params b), relu
    gemm_kernel<<<gemm_grid, 256, GEMM_SMEM>>>(nullptr, 0, 1);
    edge_kernel<<<N_NODES, HID>>>(1);
    final_kernel<<<fb, 256>>>(bias_b, 1, out, 1);

    // layer 2 (params b), no relu -> d_out
    gemm_kernel<<<gemm_grid, 256, GEMM_SMEM>>>(nullptr, 1, 1);
    edge_kernel<<<N_NODES, HID>>>(1);
    final_kernel<<<fb, 256>>>(bias_b, 2, out, 0);
}

// round 4
// speedup vs baseline: 1.0486x; 1.0486x over previous
#include <cuda_runtime.h>
#include <cstdint>

#define N_NODES 2048
#define N_EDGES 8192
#define EDGE_DIM 10
#define EH 32
#define HID 160
#define NW (HID*HID)                 // 25600
#define COL_B2 (EH*HID)              // 5120
#define COL_ROOT (EH*HID + HID)      // 5280
#define NCOLS (EH*HID + HID + HID)   // 5440

// ---------------- device scratch ----------------
__device__ float g_A[2][HID * NCOLS];
__device__ float g_h[2][N_EDGES * EH];
__device__ float g_Y[N_NODES * NCOLS];
__device__ float g_accum[N_NODES * HID];
__device__ float g_x[2][N_NODES * HID];
__device__ int   g_cnt[N_NODES];          // in-degree (dst counts)
__device__ int   g_dst[N_EDGES];
__device__ int   g_csr_off[N_NODES + 1];  // CSR by src
__device__ int   g_csr_edge[N_EDGES];

// =====================================================================
// Preprocessing: ONE block does int64-detect, edge decode, src/dst
// counts, scan, CSR fill.
// =====================================================================
__global__ __launch_bounds__(1024) void prep_kernel(const void* __restrict__ eiraw) {
    __shared__ int s_flag;
    __shared__ int s_cs[N_NODES];
    __shared__ int s_cd[N_NODES];
    __shared__ int s_a[N_NODES];
    __shared__ int s_b[N_NODES];
    int t = threadIdx.x;

    for (int i = t; i < N_NODES; i += 1024) { s_cs[i] = 0; s_cd[i] = 0; }
    if (t == 0) s_flag = 0;
    __syncthreads();

    const int* raw = (const int*)eiraw;
    int f = 0;
    for (int i = t; i < N_EDGES; i += 1024)
        if (raw[2 * i + 1] != 0) f = 1;
    if (f) atomicOr(&s_flag, 1);
    __syncthreads();
    int flag = s_flag;

    int es[8], ed[8];
    #pragma unroll
    for (int j = 0; j < 8; j++) {
        int e = t + 1024 * j;
        if (flag) {
            es[j] = raw[e]; ed[j] = raw[N_EDGES + e];
        } else {
            const long long* p = (const long long*)eiraw;
            es[j] = (int)p[e]; ed[j] = (int)p[N_EDGES + e];
        }
        atomicAdd(&s_cs[es[j]], 1);
        atomicAdd(&s_cd[ed[j]], 1);
        g_dst[e] = ed[j];
    }
    __syncthreads();

    for (int i = t; i < N_NODES; i += 1024) { g_cnt[i] = s_cd[i]; s_a[i] = s_cs[i]; }
    __syncthreads();

    int* pa = s_a; int* pb = s_b;
    for (int d = 1; d < N_NODES; d <<= 1) {
        for (int i = t; i < N_NODES; i += 1024)
            pb[i] = pa[i] + (i >= d ? pa[i - d] : 0);
        __syncthreads();
        int* tmp = pa; pa = pb; pb = tmp;
    }
    for (int i = t; i < N_NODES; i += 1024) {
        int off = (i == 0) ? 0 : pa[i - 1];
        g_csr_off[i] = off;
        pb[i] = off;
    }
    if (t == 0) g_csr_off[N_NODES] = N_EDGES;
    __syncthreads();

    #pragma unroll
    for (int j = 0; j < 8; j++) {
        int e = t + 1024 * j;
        int pos = atomicAdd(&pb[es[j]], 1);
        g_csr_edge[pos] = e;
    }
}

// =====================================================================
// Params mega-kernel: build_A (both slots) + edge MLP h (both slots)
// + zero accum.
// =====================================================================
#define NA_BLOCKS ((HID * NCOLS + 255) / 256)        // 3400
#define H_BLOCKS  (N_EDGES / 8)                      // 1024
#define Z_BLOCKS  ((N_NODES * HID + 255) / 256)      // 1280

__global__ __launch_bounds__(256) void params_kernel(
        const float* __restrict__ w2a, const float* __restrict__ b2a,
        const float* __restrict__ roota,
        const float* __restrict__ w2b, const float* __restrict__ b2b,
        const float* __restrict__ rootb,
        const float* __restrict__ ea,
        const float* __restrict__ w1a, const float* __restrict__ b1a,
        const float* __restrict__ w1b, const float* __restrict__ b1b) {
    __shared__ float sw[EDGE_DIM * EH];
    __shared__ float sb[EH];
    int b = blockIdx.x;
    int t = threadIdx.x;

    if (b < 2 * NA_BLOCKS) {
        int slot = (b >= NA_BLOCKS);
        const float* w2   = slot ? w2b : w2a;
        const float* b2   = slot ? b2b : b2a;
        const float* root = slot ? rootb : roota;
        int idx = (b - slot * NA_BLOCKS) * 256 + t;
        if (idx < HID * NCOLS) {
            int i = idx / NCOLS;
            int c = idx % NCOLS;
            float v;
            if (c < COL_B2) {
                int k = c / HID, o = c % HID;
                v = w2[k * NW + i * HID + o];
            } else if (c < COL_ROOT) {
                v = b2[i * HID + (c - COL_B2)];
            } else {
                v = root[i * HID + (c - COL_ROOT)];
            }
            g_A[slot][idx] = v;
        }
    } else if (b < 2 * NA_BLOCKS + 2 * H_BLOCKS) {
        int bb = b - 2 * NA_BLOCKS;
        int slot = (bb >= H_BLOCKS);
        const float* w1 = slot ? w1b : w1a;
        const float* b1 = slot ? b1b : b1a;
        for (int i = t; i < EDGE_DIM * EH; i += 256) sw[i] = w1[i];
        if (t < EH) sb[t] = b1[t];
        __syncthreads();
        int j  = t & 31;
        int e  = (bb - slot * H_BLOCKS) * 8 + (t >> 5);
        float acc = sb[j];
        #pragma unroll
        for (int d = 0; d < EDGE_DIM; d++)
            acc += ea[e * EDGE_DIM + d] * sw[d * EH + j];
        g_h[slot][e * EH + j] = fmaxf(acc, 0.0f);
    } else {
        int idx = (b - 2 * NA_BLOCKS - 2 * H_BLOCKS) * 256 + t;
        if (idx < N_NODES * HID) g_accum[idx] = 0.0f;
    }
}

// =====================================================================
// TF32 GEMM, cp.async double-buffered. Y[2048,5440] = X[2048,160]@A
// =====================================================================
#define BM 128
#define BN 128
#define BK 32
#define AS_STRIDE 36
#define BS_STRIDE 136
#define AS_ELEMS (BM * AS_STRIDE)     // 4608
#define BS_ELEMS (BK * BS_STRIDE)     // 4352
#define GEMM_SMEM ((AS_ELEMS + BS_ELEMS) * 2 * 4)   // 71680 B

__device__ __forceinline__ uint32_t f2tf32(float f) {
    uint32_t u;
    asm("cvt.rna.tf32.f32 %0, %1;" : "=r"(u) : "f"(f));
    return u;
}

__device__ __forceinline__ void mma_tf32(float* d, const uint32_t* a, const uint32_t* b) {
    asm volatile(
        "mma.sync.aligned.m16n8k8.row.col.f32.tf32.tf32.f32 "
        "{%0,%1,%2,%3}, {%4,%5,%6,%7}, {%8,%9}, {%0,%1,%2,%3};"
        : "+f"(d[0]), "+f"(d[1]), "+f"(d[2]), "+f"(d[3])
        : "r"(a[0]), "r"(a[1]), "r"(a[2]), "r"(a[3]), "r"(b[0]), "r"(b[1]));
}

__global__ __launch_bounds__(256, 2) void gemm_kernel(const float* __restrict__ xin,
                                                      int xsel, int aslot) {
    const float* __restrict__ X  = (xsel < 0) ? xin : g_x[xsel];
    const float* __restrict__ Bm = g_A[aslot];

    extern __shared__ float smem[];
    float* As = smem;
    float* Bs = smem + 2 * AS_ELEMS;

    int tid  = threadIdx.x;
    int lane = tid & 31;
    int w    = tid >> 5;
    int wm   = w & 1;
    int wn   = w >> 1;
    int g    = lane >> 2;
    int tig  = lane & 3;

    int n0 = blockIdx.x * BN;
    int m0 = blockIdx.y * BM;

    float acc[4][4][4];
    #pragma unroll
    for (int i = 0; i < 4; i++)
        #pragma unroll
        for (int j = 0; j < 4; j++)
            #pragma unroll
            for (int r = 0; r < 4; r++) acc[i][j][r] = 0.0f;

    auto stage = [&](int buf, int k0) {
        float* ad = As + buf * AS_ELEMS;
        float* bd = Bs + buf * BS_ELEMS;
        #pragma unroll
        for (int i = 0; i < 4; i++) {
            int s   = tid + 256 * i;
            int row = s >> 3;
            int col = (s & 7) * 4;
            uint32_t dst = (uint32_t)__cvta_generic_to_shared(&ad[row * AS_STRIDE + col]);
            const float* src = X + (size_t)(m0 + row) * HID + k0 + col;
            asm volatile("cp.async.cg.shared.global [%0], [%1], 16;"
                         :: "r"(dst), "l"(src));
        }
        #pragma unroll
        for (int i = 0; i < 4; i++) {
            int s   = tid + 256 * i;
            int row = s >> 5;
            int col = (s & 31) * 4;
            int gc  = n0 + col;
            uint32_t dst = (uint32_t)__cvta_generic_to_shared(&bd[row * BS_STRIDE + col]);
            const float* src = Bm + (size_t)(k0 + row) * NCOLS + gc;
            int bytes = (gc < NCOLS) ? 16 : 0;
            asm volatile("cp.async.cg.shared.global [%0], [%1], 16, %2;"
                         :: "r"(dst), "l"(src), "r"(bytes));
        }
        asm volatile("cp.async.commit_group;");
    };

    stage(0, 0);

    for (int it = 0; it < 5; it++) {
        if (it < 4) {
            stage((it + 1) & 1, (it + 1) * BK);
            asm volatile("cp.async.wait_group 1;");
        } else {
            asm volatile("cp.async.wait_group 0;");
        }
        __syncthreads();

        const float* as = As + (it & 1) * AS_ELEMS;
        const float* bs = Bs + (it & 1) * BS_ELEMS;

        #pragma unroll
        for (int ks = 0; ks < 4; ks++) {
            int ck = ks * 8;
            uint32_t af[4][4];
            #pragma unroll
            for (int mt = 0; mt < 4; mt++) {
                int rb = wm * 64 + mt * 16;
                af[mt][0] = f2tf32(as[(rb + g)     * AS_STRIDE + ck + tig]);
                af[mt][1] = f2tf32(as[(rb + g + 8) * AS_STRIDE + ck + tig]);
                af[mt][2] = f2tf32(as[(rb + g)     * AS_STRIDE + ck + tig + 4]);
                af[mt][3] = f2tf32(as[(rb + g + 8) * AS_STRIDE + ck + tig + 4]);
            }
            uint32_t bf[4][2];
            #pragma unroll
            for (int nt = 0; nt < 4; nt++) {
                int nc = wn * 32 + nt * 8 + g;
                bf[nt][0] = f2tf32(bs[(ck + tig)     * BS_STRIDE + nc]);
                bf[nt][1] = f2tf32(bs[(ck + tig + 4) * BS_STRIDE + nc]);
            }
            #pragma unroll
            for (int mt = 0; mt < 4; mt++)
                #pragma unroll
                for (int nt = 0; nt < 4; nt++)
                    mma_tf32(acc[mt][nt], af[mt], bf[nt]);
        }
        __syncthreads();
    }

    #pragma unroll
    for (int mt = 0; mt < 4; mt++) {
        int row = m0 + wm * 64 + mt * 16 + g;
        #pragma unroll
        for (int nt = 0; nt < 4; nt++) {
            int col = n0 + wn * 32 + nt * 8 + 2 * tig;
            if (col < NCOLS) {
                *(float2*)(g_Y + (size_t)row * NCOLS + col) =
                    make_float2(acc[mt][nt][0], acc[mt][nt][1]);
                *(float2*)(g_Y + (size_t)(row + 8) * NCOLS + col) =
                    make_float2(acc[mt][nt][2], acc[mt][nt][3]);
            }
        }
    }
}

// =====================================================================
// Edge message + scatter, CSR-by-src, high-MLP version.
// One block (256 thr) per src node: Y row staged via float4, then all
// (edge, out) pairs computed flattened across the whole block.
// =====================================================================
#define ECHUNK 32

__global__ __launch_bounds__(256) void edge_kernel(int slot) {
    __shared__ float sY[COL_ROOT];          // 21120 B
    __shared__ float sh[ECHUNK * EH];       // 4096 B
    __shared__ int   sdst[ECHUNK];
    int n = blockIdx.x;
    int t = threadIdx.x;
    int beg = g_csr_off[n];
    int end = g_csr_off[n + 1];
    if (beg == end) return;

    // stage Y row: 1320 float4, ~5.2 per thread, back-to-back issue
    const float4* Yr4 = (const float4*)(g_Y + (size_t)n * NCOLS);
    #pragma unroll
    for (int i = t; i < COL_ROOT / 4; i += 256)
        ((float4*)sY)[i] = Yr4[i];
    __syncthreads();

    for (int cb = beg; cb < end; cb += ECHUNK) {
        int m = min(end - cb, ECHUNK);
        // stage h rows + dsts for this chunk
        for (int i = t; i < m * EH; i += 256) {
            int j = i >> 5, k = i & 31;
            int e = g_csr_edge[cb + j];
            sh[i] = g_h[slot][e * EH + k];
        }
        if (t < m) sdst[t] = g_dst[g_csr_edge[cb + t]];
        __syncthreads();
        // flattened (edge, out) work: all 256 threads busy
        for (int idx = t; idx < m * HID; idx += 256) {
            int j = idx / HID, o = idx - j * HID;
            const float* hj = &sh[j * EH];
            float msg = sY[COL_B2 + o];
            #pragma unroll
            for (int k = 0; k < EH; k++) msg += hj[k] * sY[k * HID + o];
            atomicAdd(&g_accum[sdst[j] * HID + o], msg);
        }
        __syncthreads();
    }
}

// =====================================================================
// Finalize: out = act(accum/max(cnt,1) + root_term + bias); re-zero accum.
// =====================================================================
__global__ void final_kernel(const float* __restrict__ bias, int outsel,
                             float* __restrict__ dout, int relu) {
    int idx = blockIdx.x * blockDim.x + threadIdx.x;
    if (idx >= N_NODES * HID) return;
    int n = idx / HID, o = idx % HID;
    float inv = 1.0f / fmaxf((float)g_cnt[n], 1.0f);
    float v = g_accum[idx] * inv + g_Y[(size_t)n * NCOLS + COL_ROOT + o] + bias[o];
    if (relu) v = fmaxf(v, 0.0f);
    g_accum[idx] = 0.0f;
    float* dst = (outsel == 2) ? dout : g_x[outsel];
    dst[idx] = v;
}

// =====================================================================
// launch
// =====================================================================
extern "C" void kernel_launch(void* const* d_in, const int* in_sizes, int n_in,
                              void* d_out, int out_size) {
    const float* x       = (const float*)d_in[0];
    const float* ea      = (const float*)d_in[1];
    const float* w1_a    = (const float*)d_in[2];
    const float* b1_a    = (const float*)d_in[3];
    const float* w2_a    = (const float*)d_in[4];
    const float* b2_a    = (const float*)d_in[5];
    const float* root_a  = (const float*)d_in[6];
    const float* bias_a  = (const float*)d_in[7];
    const float* w1_b    = (const float*)d_in[8];
    const float* b1_b    = (const float*)d_in[9];
    const float* w2_b    = (const float*)d_in[10];
    const float* b2_b    = (const float*)d_in[11];
    const float* root_b  = (const float*)d_in[12];
    const float* bias_b  = (const float*)d_in[13];
    const void*  eidx    = d_in[14];
    float* out = (float*)d_out;

    static int smem_set = 0;
    if (!smem_set) {
        cudaFuncSetAttribute(gemm_kernel,
                             cudaFuncAttributeMaxDynamicSharedMemorySize, GEMM_SMEM);
        smem_set = 1;
    }

    prep_kernel<<<1, 1024>>>(eidx);
    params_kernel<<<2 * NA_BLOCKS + 2 * H_BLOCKS + Z_BLOCKS, 256>>>(
        w2_a, b2_a, root_a, w2_b, b2_b, root_b, ea, w1_a, b1_a, w1_b, b1_b);

    dim3 gemm_grid((NCOLS + BN - 1) / BN, N_NODES / BM);   // (43, 16)
    int nh = N_NODES * HID;
    int fb = (nh + 255) / 256;

    // layer 0 (params a), relu
    gemm_kernel<<<gemm_grid, 256, GEMM_SMEM>>>(x, -1, 0);
    edge_kernel<<<N_NODES, 256>>>(0);
    final_kernel<<<fb, 256>>>(bias_a, 0, out, 1);

    // layer 1 (params b), relu
    gemm_kernel<<<gemm_grid, 256, GEMM_SMEM>>>(nullptr, 0, 1);
    edge_kernel<<<N_NODES, 256>>>(1);
    final_kernel<<<fb, 256>>>(bias_b, 1, out, 1);

    // layer 2 (params b), no relu -> d_out
    gemm_kernel<<<gemm_grid, 256, GEMM_SMEM>>>(nullptr, 1, 1);
    edge_kernel<<<N_NODES, 256>>>(1);
    final_kernel<<<fb, 256>>>(bias_b, 2, out, 0);
}